// round 5
// baseline (speedup 1.0000x reference)
#include <cuda_runtime.h>

// NSLayer: out = x + (sum_k w[k-1] A^k + w7 I) x,  A = I - x x^T, per 8x8 matrix.
// Identity: (I - x x^T)^k x = x (I - x^T x)^k  ==>  out = x * (I + p(Abar)),
// Abar = I - x^T x is SYMMETRIC, so every Horner iterate is symmetric:
// compute only 36 upper-tri entries per matmul (288 FMA vs 512).
//
// Mapping: 1 thread = 1 matrix, fully in registers. Coalesced float4 global
// I/O staged through padded shared memory (stride 65 -> conflict-free).

#define NMAT_PER_BLOCK 128
#define SROW 65  // 64 elems + 1 pad

__device__ __forceinline__ constexpr int tix(int i, int j) {
    // upper-tri flat index, requires i <= j
    return 8 * i - (i * (i - 1)) / 2 + (j - i);
}
__device__ __forceinline__ constexpr int sym(int i, int j) {
    return (i <= j) ? tix(i, j) : tix(j, i);
}

__global__ void __launch_bounds__(NMAT_PER_BLOCK)
ns_layer_kernel(const float* __restrict__ x,
                const float* __restrict__ w,
                float* __restrict__ out) {
    __shared__ float s[NMAT_PER_BLOCK * SROW];
    const int tid = threadIdx.x;
    const long long blockBase = (long long)blockIdx.x * NMAT_PER_BLOCK * 64;

    // ---- Stage in: coalesced float4 loads -> padded smem ----
    const float4* __restrict__ gin = (const float4*)(x + blockBase);
#pragma unroll
    for (int v = 0; v < 16; v++) {
        int g4 = tid + NMAT_PER_BLOCK * v;   // float4 index in this block's chunk
        float4 d = gin[g4];
        int m = g4 >> 4;                      // matrix id (16 float4 per matrix)
        int e = (g4 & 15) << 2;               // float offset within matrix
        float* p = &s[m * SROW + e];
        p[0] = d.x; p[1] = d.y; p[2] = d.z; p[3] = d.w;
    }
    __syncthreads();

    // Polynomial coefficients: p(Abar) = c0 I + c1 Abar + ... + c7 Abar^7
    // c_k = w[k-1] for k=1..7, c0 = w7; fold the outer "+ x" into c0 (out = x @ (I + p)).
    const float c7 = w[6], c6 = w[5], c5 = w[4], c4 = w[3];
    const float c3 = w[2], c2 = w[1], c1 = w[0];
    const float c0 = w[7] + 1.0f;

    float* __restrict__ xs = &s[tid * SROW];  // this thread's matrix (bank-conflict-free)

    // ---- Abar = I - x^T x (upper triangle only) ----
    float Ab[36];
    {
        float X[64];
#pragma unroll
        for (int i = 0; i < 64; i++) X[i] = xs[i];
#pragma unroll
        for (int i = 0; i < 8; i++) {
#pragma unroll
            for (int j = i; j < 8; j++) {
                float acc = X[0 * 8 + i] * X[0 * 8 + j];
#pragma unroll
                for (int k = 1; k < 8; k++)
                    acc = fmaf(X[k * 8 + i], X[k * 8 + j], acc);
                Ab[tix(i, j)] = (i == j ? 1.0f : 0.0f) - acc;
            }
        }
    }  // X dies here

    // ---- Horner on symmetric matrices:  T <- Abar*T + c_j I ----
    float T[36];
#pragma unroll
    for (int i = 0; i < 8; i++)
#pragma unroll
        for (int j = i; j < 8; j++)
            T[tix(i, j)] = c7 * Ab[tix(i, j)] + (i == j ? c6 : 0.0f);

    const float cs[6] = {c5, c4, c3, c2, c1, c0};
#pragma unroll
    for (int step = 0; step < 6; step++) {
        float N[36];
#pragma unroll
        for (int i = 0; i < 8; i++) {
#pragma unroll
            for (int j = i; j < 8; j++) {
                float acc = Ab[sym(i, 0)] * T[sym(0, j)];
#pragma unroll
                for (int m = 1; m < 8; m++)
                    acc = fmaf(Ab[sym(i, m)], T[sym(m, j)], acc);
                N[tix(i, j)] = acc + (i == j ? cs[step] : 0.0f);
            }
        }
#pragma unroll
        for (int q = 0; q < 36; q++) T[q] = N[q];
    }

    // ---- out = x @ T  (T symmetric, includes the +I and +w7 I terms) ----
    // Row i of out depends only on row i of x -> overwrite smem row in place.
#pragma unroll
    for (int i = 0; i < 8; i++) {
        float xr[8];
#pragma unroll
        for (int k = 0; k < 8; k++) xr[k] = xs[i * 8 + k];
        float o[8];
#pragma unroll
        for (int j = 0; j < 8; j++) {
            float acc = xr[0] * T[sym(0, j)];
#pragma unroll
            for (int k = 1; k < 8; k++)
                acc = fmaf(xr[k], T[sym(k, j)], acc);
            o[j] = acc;
        }
#pragma unroll
        for (int j = 0; j < 8; j++) xs[i * 8 + j] = o[j];
    }
    __syncthreads();

    // ---- Stage out: padded smem -> coalesced float4 stores ----
    float4* __restrict__ gout = (float4*)(out + blockBase);
#pragma unroll
    for (int v = 0; v < 16; v++) {
        int g4 = tid + NMAT_PER_BLOCK * v;
        int m = g4 >> 4;
        int e = (g4 & 15) << 2;
        const float* p = &s[m * SROW + e];
        float4 d;
        d.x = p[0]; d.y = p[1]; d.z = p[2]; d.w = p[3];
        gout[g4] = d;
    }
}

extern "C" void kernel_launch(void* const* d_in, const int* in_sizes, int n_in,
                              void* d_out, int out_size) {
    const float* x = (const float*)d_in[0];     // (2048,128,8,8) fp32
    const float* w = (const float*)d_in[1];     // (14,) fp32
    float* out = (float*)d_out;

    int nmat = in_sizes[0] / 64;                // 262144
    int grid = nmat / NMAT_PER_BLOCK;           // 2048
    ns_layer_kernel<<<grid, NMAT_PER_BLOCK>>>(x, w, out);
}

// round 6
// speedup vs baseline: 1.2145x; 1.2145x over previous
#include <cuda_runtime.h>

// NSLayer via identity (I - x x^T)^k x = x (I - x^T x)^k:
//   out = x @ T,  T = sum_k c_k Abar^k,  Abar = I - x^T x (symmetric).
// Horner on symmetric iterates, with inner products done as packed f32x2
// (SASS FFMA2, 2 FMA/lane/issue) and only upper-triangular pairs computed;
// lower pairs mirrored via lane swaps on the ALU pipe.

#define NMB 128
#define SROW 66   // even -> 8-byte-aligned rows for b64 smem accesses

typedef unsigned long long u64;

__device__ __forceinline__ u64 pack2(float a, float b) {
    u64 r; asm("mov.b64 %0, {%1, %2};" : "=l"(r) : "f"(a), "f"(b)); return r;
}
__device__ __forceinline__ void unpack2(u64 v, float &a, float &b) {
    asm("mov.b64 {%0, %1}, %2;" : "=f"(a), "=f"(b) : "l"(v));
}
__device__ __forceinline__ u64 fma2(u64 a, u64 b, u64 c) {
    u64 d; asm("fma.rn.f32x2 %0, %1, %2, %3;" : "=l"(d) : "l"(a), "l"(b), "l"(c)); return d;
}
__device__ __forceinline__ u64 mul2(u64 a, u64 b) {
    u64 d; asm("mul.rn.f32x2 %0, %1, %2;" : "=l"(d) : "l"(a), "l"(b)); return d;
}

__device__ __forceinline__ constexpr int tix(int i, int j) {  // i <= j
    return 8 * i - (i * (i - 1)) / 2 + (j - i);
}
__device__ __forceinline__ constexpr int symq(int i, int j) {
    return (i <= j) ? tix(i, j) : tix(j, i);
}
// storage index for upper packed pairs: row i holds pairs p = i/2 .. 3
__device__ __forceinline__ constexpr int nustart(int i) {
    return (i == 0) ? 0 : (i == 1) ? 4 : (i == 2) ? 8 : (i == 3) ? 11
         : (i == 4) ? 14 : (i == 5) ? 16 : (i == 6) ? 18 : 19;
}
__device__ __forceinline__ constexpr int nux(int i, int p) { return nustart(i) + (p - i / 2); }

__global__ void __launch_bounds__(NMB)
ns_kernel(const float* __restrict__ x, const float* __restrict__ w,
          float* __restrict__ out)
{
    __shared__ float s[NMB * SROW];
    const int tid = threadIdx.x;
    const long long base = (long long)blockIdx.x * NMB * 64;

    // ---- stage in: coalesced float4 gmem -> padded smem (float2 stores, 8B aligned) ----
    const float4* __restrict__ gin = (const float4*)(x + base);
#pragma unroll
    for (int v = 0; v < 16; v++) {
        int g4 = tid + NMB * v;
        float4 d = gin[g4];
        int m = g4 >> 4, e = (g4 & 15) << 2;
        float2* p = (float2*)&s[m * SROW + e];
        p[0] = make_float2(d.x, d.y);
        p[1] = make_float2(d.z, d.w);
    }
    __syncthreads();

    const float c7 = w[6], c6 = w[5];
    const float cs[6] = { w[4], w[3], w[2], w[1], w[0], w[7] + 1.0f };

    float* __restrict__ xs = &s[tid * SROW];

    // ---- Abar = I - x^T x: scalar, upper triangle (yields the scalars we broadcast) ----
    float Ab[36];
    {
        float X[64];
#pragma unroll
        for (int i = 0; i < 64; i++) X[i] = xs[i];
#pragma unroll
        for (int i = 0; i < 8; i++) {
#pragma unroll
            for (int j = i; j < 8; j++) {
                float acc = X[0 * 8 + i] * X[0 * 8 + j];
#pragma unroll
                for (int k = 1; k < 8; k++)
                    acc = fmaf(X[k * 8 + i], X[k * 8 + j], acc);
                Ab[tix(i, j)] = (i == j ? 1.0f : 0.0f) - acc;
            }
        }
    }  // X dies here

    // ---- broadcast pairs {a,a}, reused by all 6 Horner steps ----
    u64 Abb[36];
#pragma unroll
    for (int q = 0; q < 36; q++) Abb[q] = pack2(Ab[q], Ab[q]);

    // ---- T = c7*Abar + c6*I, dense packed rows (pair p covers cols 2p,2p+1) ----
    u64 T[32];
#pragma unroll
    for (int i = 0; i < 8; i++) {
#pragma unroll
        for (int p = 0; p < 4; p++) {
            float lo = c7 * Ab[symq(i, 2 * p)]     + ((i == 2 * p)     ? c6 : 0.0f);
            float hi = c7 * Ab[symq(i, 2 * p + 1)] + ((i == 2 * p + 1) ? c6 : 0.0f);
            T[i * 4 + p] = pack2(lo, hi);
        }
    }  // Ab dies here

    // ---- 6 Horner steps: T <- Abar*T + cs[s]*I (upper pairs only, then mirror) ----
#pragma unroll
    for (int sIdx = 0; sIdx < 6; sIdx++) {
        u64 NU[20];
#pragma unroll
        for (int i = 0; i < 8; i++) {
#pragma unroll
            for (int p = i / 2; p < 4; p++) {
                u64 acc;
                if (i == 2 * p)          acc = pack2(cs[sIdx], 0.0f);
                else if (i == 2 * p + 1) acc = pack2(0.0f, cs[sIdx]);
                else                     acc = 0ULL;
#pragma unroll
                for (int m = 0; m < 8; m++)
                    acc = fma2(Abb[symq(i, m)], T[m * 4 + p], acc);
                NU[nux(i, p)] = acc;
            }
        }
        // rebuild dense packed T; lower pairs mirrored by symmetry:
        // T[i][{2p,2p+1}] = {N[2p][i], N[2p+1][i]}  (lane selects on ALU pipe)
#pragma unroll
        for (int i = 0; i < 8; i++) {
#pragma unroll
            for (int p = 0; p < 4; p++) {
                if (p >= i / 2) {
                    T[i * 4 + p] = NU[nux(i, p)];
                } else {
                    float a0, a1, b0, b1;
                    unpack2(NU[nux(2 * p,     i / 2)], a0, a1);
                    unpack2(NU[nux(2 * p + 1, i / 2)], b0, b1);
                    float v0 = (i & 1) ? a1 : a0;
                    float v1 = (i & 1) ? b1 : b0;
                    T[i * 4 + p] = pack2(v0, v1);
                }
            }
        }
    }

    // ---- out = x @ T, row-wise in place (row i read fully before written) ----
#pragma unroll
    for (int i = 0; i < 8; i++) {
        float xr[8];
#pragma unroll
        for (int q = 0; q < 4; q++) {
            u64 v = *(const u64*)&xs[i * 8 + 2 * q];
            unpack2(v, xr[2 * q], xr[2 * q + 1]);
        }
        u64 xb[8];
#pragma unroll
        for (int k = 0; k < 8; k++) xb[k] = pack2(xr[k], xr[k]);
#pragma unroll
        for (int p = 0; p < 4; p++) {
            u64 acc = mul2(xb[0], T[0 * 4 + p]);
#pragma unroll
            for (int k = 1; k < 8; k++)
                acc = fma2(xb[k], T[k * 4 + p], acc);
            *(u64*)&xs[i * 8 + 2 * p] = acc;
        }
    }
    __syncthreads();

    // ---- stage out: padded smem -> coalesced float4 gmem ----
    float4* __restrict__ gout = (float4*)(out + base);
#pragma unroll
    for (int v = 0; v < 16; v++) {
        int g4 = tid + NMB * v;
        int m = g4 >> 4, e = (g4 & 15) << 2;
        const float2* p = (const float2*)&s[m * SROW + e];
        float2 a = p[0], b = p[1];
        gout[g4] = make_float4(a.x, a.y, b.x, b.y);
    }
}

extern "C" void kernel_launch(void* const* d_in, const int* in_sizes, int n_in,
                              void* d_out, int out_size) {
    const float* x = (const float*)d_in[0];   // (2048,128,8,8) fp32
    const float* w = (const float*)d_in[1];   // (14,) fp32
    float* out = (float*)d_out;

    int nmat = in_sizes[0] / 64;              // 262144
    int grid = nmat / NMB;                    // 2048
    ns_kernel<<<grid, NMB>>>(x, w, out);
}